// round 8
// baseline (speedup 1.0000x reference)
#include <cuda_runtime.h>
#include <cuda_fp16.h>
#include <cstdint>

#define MAXN 50000
#define MAXE 800000
#define HDIM 128
#define FE 64
#define FN 92
#define KX 192          // HDIM + FE
#define NLAYER 3
#define BN_EPS 1e-3f

// ---------------- scratch (static device globals; no allocation) ----------------
__device__ float  d_h[MAXN * HDIM];        // node features (fp32, for residual+pool)
__device__ __half d_hh[MAXN * HDIM];       // fp16 mirror of h (SpMM gather source)
__device__ __half d_Xh[MAXN * KX];         // fp16 [ sum h[col] | sum edge_attr ]
__device__ int    d_cnt[MAXN];             // in-degree counts
__device__ int    d_off[MAXN + 1];         // CSR offsets by destination (row)
__device__ int    d_cur[MAXN];             // scatter cursors
__device__ int    d_cols[MAXE];            // source node (col) sorted by destination
__device__ int    d_eid[MAXE];             // original edge id sorted by destination
__device__ int    d_bsum[64];              // per-block scan totals
__device__ int    d_bbase[64];             // per-block scan bases

struct __align__(8) H4 { __half2 a, b; };

// ---------------- CSR build ----------------
__global__ void k_zero_cnt(int n) {
    int i = blockIdx.x * blockDim.x + threadIdx.x;
    if (i < n) d_cnt[i] = 0;
}

__global__ void k_hist(const int* __restrict__ ei, int E) {
    int e = blockIdx.x * blockDim.x + threadIdx.x;
    if (e < E) atomicAdd(&d_cnt[ei[e]], 1);
}

__global__ void k_scan1(int N) {
    __shared__ int s[32];
    int t = threadIdx.x;
    int i = blockIdx.x * 1024 + t;
    int lane = t & 31, w = t >> 5;
    int c = (i < N) ? d_cnt[i] : 0;
    int v = c;
#pragma unroll
    for (int d = 1; d < 32; d <<= 1) {
        int u = __shfl_up_sync(0xffffffffu, v, d);
        if (lane >= d) v += u;
    }
    if (lane == 31) s[w] = v;
    __syncthreads();
    if (w == 0) {
        int sv = s[lane];
#pragma unroll
        for (int d = 1; d < 32; d <<= 1) {
            int u = __shfl_up_sync(0xffffffffu, sv, d);
            if (lane >= d) sv += u;
        }
        s[lane] = sv;
    }
    __syncthreads();
    int base = (w > 0) ? s[w - 1] : 0;
    int incl = v + base;
    if (i < N) d_off[i] = incl - c;
    if (t == 1023) d_bsum[blockIdx.x] = incl;
}

__global__ void k_scan2(int NB) {
    __shared__ int s[2];
    int t = threadIdx.x;
    int lane = t & 31, w = t >> 5;
    int c = (t < NB) ? d_bsum[t] : 0;
    int v = c;
#pragma unroll
    for (int d = 1; d < 32; d <<= 1) {
        int u = __shfl_up_sync(0xffffffffu, v, d);
        if (lane >= d) v += u;
    }
    if (lane == 31) s[w] = v;
    __syncthreads();
    int base = (w > 0) ? s[0] : 0;
    if (t < NB) d_bbase[t] = v + base - c;
}

__global__ void k_scan3(int N, int E) {
    int i = blockIdx.x * blockDim.x + threadIdx.x;
    if (i < N) {
        int v = d_off[i] + d_bbase[i >> 10];
        d_off[i] = v;
        d_cur[i] = v;
    }
    if (i == 0) d_off[N] = E;
}

__global__ void k_scatter(const int* __restrict__ ei, int E) {
    int e = blockIdx.x * blockDim.x + threadIdx.x;
    if (e < E) {
        int r = ei[e];
        int c = ei[E + e];
        int p = atomicAdd(&d_cur[r], 1);
        d_cols[p] = c;
        d_eid[p]  = e;
    }
}

// ---------------- SpMM: Xh[:,0:128] = sum_{in-edges} h_fp16[col]  (fp32 acc, fp16 store)
// FIRST==1 additionally computes Xh[:,128:192] = sum_{in-edges} edge_attr[eid]
template <int FIRST>
__launch_bounds__(256)
__global__ void k_spmm(const float* __restrict__ ea, int N) {
    int gw   = (blockIdx.x * blockDim.x + threadIdx.x) >> 5;
    int lane = threadIdx.x & 31;
    if (gw >= N) return;
    int lo = d_off[gw], hi = d_off[gw + 1];
    float4 acc = make_float4(0.f, 0.f, 0.f, 0.f);
    float2 eacc = make_float2(0.f, 0.f);
    int j = lo;
    for (; j + 4 <= hi; j += 4) {
        int c0 = d_cols[j],     c1 = d_cols[j + 1];
        int c2 = d_cols[j + 2], c3 = d_cols[j + 3];
        H4 v0 = *(const H4*)(d_hh + (size_t)c0 * HDIM + lane * 4);
        H4 v1 = *(const H4*)(d_hh + (size_t)c1 * HDIM + lane * 4);
        H4 v2 = *(const H4*)(d_hh + (size_t)c2 * HDIM + lane * 4);
        H4 v3 = *(const H4*)(d_hh + (size_t)c3 * HDIM + lane * 4);
        if (FIRST) {
            int e0 = d_eid[j],     e1 = d_eid[j + 1];
            int e2 = d_eid[j + 2], e3 = d_eid[j + 3];
            float2 w0 = *(const float2*)(ea + (size_t)e0 * FE + lane * 2);
            float2 w1 = *(const float2*)(ea + (size_t)e1 * FE + lane * 2);
            float2 w2 = *(const float2*)(ea + (size_t)e2 * FE + lane * 2);
            float2 w3 = *(const float2*)(ea + (size_t)e3 * FE + lane * 2);
            eacc.x += (w0.x + w1.x) + (w2.x + w3.x);
            eacc.y += (w0.y + w1.y) + (w2.y + w3.y);
        }
        float2 a0 = __half22float2(v0.a), b0 = __half22float2(v0.b);
        float2 a1 = __half22float2(v1.a), b1 = __half22float2(v1.b);
        float2 a2 = __half22float2(v2.a), b2 = __half22float2(v2.b);
        float2 a3 = __half22float2(v3.a), b3 = __half22float2(v3.b);
        acc.x += (a0.x + a1.x) + (a2.x + a3.x);
        acc.y += (a0.y + a1.y) + (a2.y + a3.y);
        acc.z += (b0.x + b1.x) + (b2.x + b3.x);
        acc.w += (b0.y + b1.y) + (b2.y + b3.y);
    }
    for (; j < hi; j++) {
        int c0 = d_cols[j];
        H4 v0 = *(const H4*)(d_hh + (size_t)c0 * HDIM + lane * 4);
        if (FIRST) {
            int e0 = d_eid[j];
            float2 w0 = *(const float2*)(ea + (size_t)e0 * FE + lane * 2);
            eacc.x += w0.x; eacc.y += w0.y;
        }
        float2 a0 = __half22float2(v0.a), b0 = __half22float2(v0.b);
        acc.x += a0.x; acc.y += a0.y; acc.z += b0.x; acc.w += b0.y;
    }
    H4 st;
    st.a = __floats2half2_rn(acc.x, acc.y);
    st.b = __floats2half2_rn(acc.z, acc.w);
    *(H4*)(d_Xh + (size_t)gw * KX + lane * 4) = st;
    if (FIRST)
        *(__half2*)(d_Xh + (size_t)gw * KX + HDIM + lane * 2) =
            __floats2half2_rn(eacc.x, eacc.y);
}

// ---------------- tf32 tensor-core GEMM (embedding): h = relu(x@W_emb + b) ----------------
__device__ __forceinline__ uint32_t f2tf32(float f) {
    uint32_t r;
    asm("cvt.rna.tf32.f32 %0, %1;" : "=r"(r) : "f"(f));
    return r;
}

template <int K>
__launch_bounds__(256)
__global__ void k_gemm_tc(const float* __restrict__ Ain,
                          const float* __restrict__ W,
                          const float* __restrict__ bias,
                          int N) {
    constexpr int KC = 32;
    constexpr int KTILES = (K + KC - 1) / KC;
    constexpr int AS_STRIDE = 36;
    constexpr int BS_STRIDE = 132;
    __shared__ __align__(16) float As[128 * AS_STRIDE];
    __shared__ __align__(16) float Bs[32 * BS_STRIDE];

    const int tid  = threadIdx.x;
    const int wid  = tid >> 5;
    const int lane = tid & 31;
    const int warp_m = wid & 3;
    const int warp_n = wid >> 2;
    const int gID = lane >> 2;
    const int tig = lane & 3;
    const int rowBase = blockIdx.x * 128;

    float acc[2][8][4];
#pragma unroll
    for (int mf = 0; mf < 2; mf++)
#pragma unroll
        for (int nf = 0; nf < 8; nf++)
#pragma unroll
            for (int c = 0; c < 4; c++) acc[mf][nf][c] = 0.f;

    for (int kt = 0; kt < KTILES; kt++) {
        const int k0 = kt * KC;
        {
            int r = tid >> 3;
            int k4 = (tid & 7) * 4;
#pragma unroll
            for (int it = 0; it < 4; it++) {
                int row = r + it * 32;
                int grow = rowBase + row;
                int kg = k0 + k4;
                float4 v = make_float4(0.f, 0.f, 0.f, 0.f);
                if (grow < N && kg + 4 <= K)
                    v = *(const float4*)(Ain + (size_t)grow * K + kg);
                *(float4*)&As[row * AS_STRIDE + k4] = v;
            }
        }
        {
            int kk = tid >> 5;
            int c4 = (tid & 31) * 4;
#pragma unroll
            for (int it = 0; it < 4; it++) {
                int krow = kk + it * 8;
                int kg = k0 + krow;
                float4 v = make_float4(0.f, 0.f, 0.f, 0.f);
                if (kg < K)
                    v = *(const float4*)(W + (size_t)kg * HDIM + c4);
                *(float4*)&Bs[krow * BS_STRIDE + c4] = v;
            }
        }
        __syncthreads();

#pragma unroll
        for (int k8 = 0; k8 < KC / 8; k8++) {
            const int kb = k8 * 8;
            uint32_t bfr[8][2];
#pragma unroll
            for (int nf = 0; nf < 8; nf++) {
                int col = warp_n * 64 + nf * 8 + gID;
                bfr[nf][0] = f2tf32(Bs[(kb + tig) * BS_STRIDE + col]);
                bfr[nf][1] = f2tf32(Bs[(kb + tig + 4) * BS_STRIDE + col]);
            }
#pragma unroll
            for (int mf = 0; mf < 2; mf++) {
                int r0 = warp_m * 32 + mf * 16 + gID;
                uint32_t a0 = f2tf32(As[r0 * AS_STRIDE + kb + tig]);
                uint32_t a1 = f2tf32(As[(r0 + 8) * AS_STRIDE + kb + tig]);
                uint32_t a2 = f2tf32(As[r0 * AS_STRIDE + kb + tig + 4]);
                uint32_t a3 = f2tf32(As[(r0 + 8) * AS_STRIDE + kb + tig + 4]);
#pragma unroll
                for (int nf = 0; nf < 8; nf++) {
                    asm volatile(
                        "mma.sync.aligned.m16n8k8.row.col.f32.tf32.tf32.f32 "
                        "{%0,%1,%2,%3}, {%4,%5,%6,%7}, {%8,%9}, {%0,%1,%2,%3};\n"
                        : "+f"(acc[mf][nf][0]), "+f"(acc[mf][nf][1]),
                          "+f"(acc[mf][nf][2]), "+f"(acc[mf][nf][3])
                        : "r"(a0), "r"(a1), "r"(a2), "r"(a3),
                          "r"(bfr[nf][0]), "r"(bfr[nf][1]));
                }
            }
        }
        __syncthreads();
    }

#pragma unroll
    for (int mf = 0; mf < 2; mf++) {
        int r0 = rowBase + warp_m * 32 + mf * 16 + gID;
        int r1 = r0 + 8;
#pragma unroll
        for (int nf = 0; nf < 8; nf++) {
            int c0 = warp_n * 64 + nf * 8 + 2 * tig;
#pragma unroll
            for (int cc = 0; cc < 2; cc++) {
                int c = c0 + cc;
                float b = bias[c];
                if (r0 < N) {
                    float v = fmaxf(acc[mf][nf][cc] + b, 0.f);
                    d_h[(size_t)r0 * HDIM + c] = v;
                    d_hh[(size_t)r0 * HDIM + c] = __float2half_rn(v);
                }
                if (r1 < N) {
                    float v = fmaxf(acc[mf][nf][2 + cc] + b, 0.f);
                    d_h[(size_t)r1 * HDIM + c] = v;
                    d_hh[(size_t)r1 * HDIM + c] = __float2half_rn(v);
                }
            }
        }
    }
}

// ---------------- fp16 tensor-core layer GEMM: d_h += relu(BN(Xh@W/deg + b)) ----------------
__launch_bounds__(256)
__global__ void k_gemm_h(const float* __restrict__ W,
                         const float* __restrict__ bias,
                         const float* __restrict__ gamma,
                         const float* __restrict__ beta,
                         int N) {
    constexpr int K = KX;          // 192
    constexpr int KC = 32;
    constexpr int KTILES = K / KC; // 6
    constexpr int AST = 40;        // half stride (80 B), conflict-free fragment LDS
    constexpr int BST = 40;
    __shared__ __align__(16) __half As[128 * AST];   // [row][k]
    __shared__ __align__(16) __half Bs[128 * BST];   // [n][k] (transposed W)

    const int tid  = threadIdx.x;
    const int wid  = tid >> 5;
    const int lane = tid & 31;
    const int warp_m = wid & 3;
    const int warp_n = wid >> 2;
    const int gID = lane >> 2;
    const int tig = lane & 3;
    const int rowBase = blockIdx.x * 128;

    float acc[2][8][4];
#pragma unroll
    for (int mf = 0; mf < 2; mf++)
#pragma unroll
        for (int nf = 0; nf < 8; nf++)
#pragma unroll
            for (int c = 0; c < 4; c++) acc[mf][nf][c] = 0.f;

    for (int kt = 0; kt < KTILES; kt++) {
        const int k0 = kt * KC;
        // stage A: 128 rows x 32 halves (16B = 8 halves per load)
        {
#pragma unroll
            for (int it = 0; it < 2; it++) {
                int idx = tid + it * 256;       // 0..511
                int row = idx >> 2;             // 0..127
                int k8 = (idx & 3) * 8;         // 0,8,16,24
                int grow = rowBase + row;
                uint4 v = make_uint4(0u, 0u, 0u, 0u);
                if (grow < N)
                    v = *(const uint4*)(d_Xh + (size_t)grow * K + k0 + k8);
                *(uint4*)&As[row * AST + k8] = v;
            }
        }
        // stage B transposed: W[k][n] fp32 -> Bs[n][k] fp16
        {
#pragma unroll
            for (int i = 0; i < 16; i++) {
                int idx = tid + i * 256;        // 0..4095
                int kk = idx >> 7;              // 0..31
                int c  = idx & 127;             // 0..127
                Bs[c * BST + kk] = __float2half_rn(W[(size_t)(k0 + kk) * HDIM + c]);
            }
        }
        __syncthreads();

#pragma unroll
        for (int ks = 0; ks < 2; ks++) {        // two k16 steps
            const int kb = ks * 16;
            uint32_t bfr[8][2];
#pragma unroll
            for (int nf = 0; nf < 8; nf++) {
                int col = warp_n * 64 + nf * 8 + gID;
                bfr[nf][0] = *(const uint32_t*)&Bs[col * BST + kb + 2 * tig];
                bfr[nf][1] = *(const uint32_t*)&Bs[col * BST + kb + 8 + 2 * tig];
            }
#pragma unroll
            for (int mf = 0; mf < 2; mf++) {
                int r0 = warp_m * 32 + mf * 16 + gID;
                uint32_t a0 = *(const uint32_t*)&As[r0 * AST + kb + 2 * tig];
                uint32_t a1 = *(const uint32_t*)&As[(r0 + 8) * AST + kb + 2 * tig];
                uint32_t a2 = *(const uint32_t*)&As[r0 * AST + kb + 8 + 2 * tig];
                uint32_t a3 = *(const uint32_t*)&As[(r0 + 8) * AST + kb + 8 + 2 * tig];
#pragma unroll
                for (int nf = 0; nf < 8; nf++) {
                    asm volatile(
                        "mma.sync.aligned.m16n8k16.row.col.f32.f16.f16.f32 "
                        "{%0,%1,%2,%3}, {%4,%5,%6,%7}, {%8,%9}, {%0,%1,%2,%3};\n"
                        : "+f"(acc[mf][nf][0]), "+f"(acc[mf][nf][1]),
                          "+f"(acc[mf][nf][2]), "+f"(acc[mf][nf][3])
                        : "r"(a0), "r"(a1), "r"(a2), "r"(a3),
                          "r"(bfr[nf][0]), "r"(bfr[nf][1]));
                }
            }
        }
        __syncthreads();
    }

    const float sc = rsqrtf(1.f + BN_EPS);
#pragma unroll
    for (int mf = 0; mf < 2; mf++) {
        int r0 = rowBase + warp_m * 32 + mf * 16 + gID;
        int r1 = r0 + 8;
        float inv0 = 1.f, inv1 = 1.f;
        if (r0 < N) inv0 = 1.f / (float)max(d_cnt[r0], 1);
        if (r1 < N) inv1 = 1.f / (float)max(d_cnt[r1], 1);
#pragma unroll
        for (int nf = 0; nf < 8; nf++) {
            int c0 = warp_n * 64 + nf * 8 + 2 * tig;
#pragma unroll
            for (int cc = 0; cc < 2; cc++) {
                int c = c0 + cc;
                float b = bias[c];
                float g = gamma[c] * sc;
                float be = beta[c];
                if (r0 < N) {
                    float v = acc[mf][nf][cc] * inv0 + b;
                    v = v * g + be;
                    float nh = d_h[(size_t)r0 * HDIM + c] + fmaxf(v, 0.f);
                    d_h[(size_t)r0 * HDIM + c] = nh;
                    d_hh[(size_t)r0 * HDIM + c] = __float2half_rn(nh);
                }
                if (r1 < N) {
                    float v = acc[mf][nf][2 + cc] * inv1 + b;
                    v = v * g + be;
                    float nh = d_h[(size_t)r1 * HDIM + c] + fmaxf(v, 0.f);
                    d_h[(size_t)r1 * HDIM + c] = nh;
                    d_hh[(size_t)r1 * HDIM + c] = __float2half_rn(nh);
                }
            }
        }
    }
}

// ---------------- fused mean-pool + hidden + head (batch_idx sorted) ----------------
__launch_bounds__(128)
__global__ void k_head(const int* __restrict__ batch,
                       const float* __restrict__ Wh,
                       const float* __restrict__ bh,
                       const float* __restrict__ Wout,
                       const float* __restrict__ bout,
                       float* __restrict__ out, int N) {
    int b = blockIdx.x;
    int t = threadIdx.x;
    __shared__ float gv[HDIM];
    __shared__ float red[HDIM];
    __shared__ int srange[2];
    if (t < 2) {
        int v = b + t;
        int lo = 0, hi = N;
        while (lo < hi) {
            int m = (lo + hi) >> 1;
            if (batch[m] < v) lo = m + 1; else hi = m;
        }
        srange[t] = lo;
    }
    __syncthreads();
    int lo = srange[0], hi = srange[1];
    float s = 0.f;
    for (int r = lo; r < hi; r++) s += d_h[(size_t)r * HDIM + t];
    gv[t] = s / (float)max(hi - lo, 1);
    __syncthreads();
    float hd = bh[t];
#pragma unroll 8
    for (int k = 0; k < HDIM; k++) hd = fmaf(gv[k], Wh[k * HDIM + t], hd);
    hd = fmaxf(hd, 0.f);
    red[t] = hd * Wout[t];
    __syncthreads();
    for (int s2 = 64; s2 > 0; s2 >>= 1) {
        if (t < s2) red[t] += red[t + s2];
        __syncthreads();
    }
    if (t == 0) out[b] = red[0] + bout[0];
}

// ---------------- launch ----------------
extern "C" void kernel_launch(void* const* d_in, const int* in_sizes, int n_in,
                              void* d_out, int out_size) {
    const float* x     = (const float*)d_in[0];
    const int*   ei    = (const int*)  d_in[1];
    const float* ea    = (const float*)d_in[2];
    const int*   batch = (const int*)  d_in[3];
    const float* W_emb = (const float*)d_in[4];
    const float* b_emb = (const float*)d_in[5];
    const float* Wc    = (const float*)d_in[6];
    const float* bc    = (const float*)d_in[7];
    const float* gamma = (const float*)d_in[8];
    const float* beta  = (const float*)d_in[9];
    const float* Wh    = (const float*)d_in[10];
    const float* bh    = (const float*)d_in[11];
    const float* Wout  = (const float*)d_in[12];
    const float* bout  = (const float*)d_in[13];
    float* out = (float*)d_out;

    int N = in_sizes[0] / FN;
    int E = in_sizes[1] / 2;
    int G = out_size;
    int NB = (N + 1023) / 1024;

    k_zero_cnt<<<(N + 255) / 256, 256>>>(N);               // 0
    k_hist<<<(E + 255) / 256, 256>>>(ei, E);               // 1
    k_scan1<<<NB, 1024>>>(N);                              // 2
    // embedding at launch index 3 -> ncu window profiles this
    k_gemm_tc<FN><<<(N + 127) / 128, 256>>>(x, W_emb, b_emb, N);  // 3
    k_scan2<<<1, 64>>>(NB);                                // 4
    k_scan3<<<NB, 1024>>>(N, E);                           // 5
    k_scatter<<<(E + 255) / 256, 256>>>(ei, E);            // 6

    // layer 0: fused h-gather + edge-attr aggregation
    k_spmm<1><<<(N * 32 + 255) / 256, 256>>>(ea, N);
    k_gemm_h<<<(N + 127) / 128, 256>>>(Wc, bc, gamma, beta, N);

    for (int l = 1; l < NLAYER; l++) {
        k_spmm<0><<<(N * 32 + 255) / 256, 256>>>(ea, N);
        k_gemm_h<<<(N + 127) / 128, 256>>>(Wc + (size_t)l * KX * HDIM,
                                           bc + l * HDIM, gamma + l * HDIM,
                                           beta + l * HDIM, N);
    }

    k_head<<<G, 128>>>(batch, Wh, bh, Wout, bout, out, N);
}

// round 9
// speedup vs baseline: 1.1156x; 1.1156x over previous
#include <cuda_runtime.h>
#include <cuda_fp16.h>
#include <cstdint>

#define MAXN 50000
#define MAXE 800000
#define HDIM 128
#define FE 64
#define FN 92
#define KE 96           // padded emb K
#define KX 192          // HDIM + FE
#define NLAYER 3
#define BN_EPS 1e-3f

// ---------------- scratch (static device globals; no allocation) ----------------
__device__ float  d_h[MAXN * HDIM];         // node features (fp32, residual+pool)
__device__ __half d_hh[MAXN * HDIM];        // fp16 mirror of h (SpMM gather source)
__device__ __half d_Xh[MAXN * KX];          // fp16 [ sum h[col] | sum edge_attr ]
__device__ __half d_xh[MAXN * KE];          // fp16 padded node input features
__device__ __half d_Wch[NLAYER * HDIM * KX];  // fp16 transposed Wc: [l][n][k]
__device__ __half d_Wembh[HDIM * KE];       // fp16 transposed padded W_emb: [n][k]
__device__ int    d_cnt[MAXN];
__device__ int    d_off[MAXN + 1];
__device__ int    d_cur[MAXN];
__device__ int    d_cols[MAXE];
__device__ int    d_eid[MAXE];
__device__ int    d_bsum[64];
__device__ int    d_bbase[64];

struct __align__(8) H4 { __half2 a, b; };

// ---------------- weight/input prep ----------------
__global__ void k_prep_w(const float* __restrict__ Wc, const float* __restrict__ W_emb) {
    int i = blockIdx.x * blockDim.x + threadIdx.x;
    int nw = NLAYER * HDIM * KX;             // 73728
    if (i < nw) {
        int l = i / (HDIM * KX);
        int r = i - l * (HDIM * KX);
        int n = r / KX;
        int k = r - n * KX;
        d_Wch[i] = __float2half_rn(Wc[(size_t)l * KX * HDIM + (size_t)k * HDIM + n]);
    } else if (i < nw + HDIM * KE) {
        int r = i - nw;
        int n = r / KE;
        int k = r - n * KE;
        d_Wembh[r] = (k < FN) ? __float2half_rn(W_emb[(size_t)k * HDIM + n])
                              : __half(0.f);
    }
}

__global__ void k_conv_x(const float* __restrict__ x, int N) {
    int i = blockIdx.x * blockDim.x + threadIdx.x;
    if (i >= N * KE) return;
    int row = i / KE;
    int k = i - row * KE;
    d_xh[i] = (k < FN) ? __float2half_rn(x[(size_t)row * FN + k]) : __half(0.f);
}

// ---------------- CSR build ----------------
__global__ void k_zero_cnt(int n) {
    int i = blockIdx.x * blockDim.x + threadIdx.x;
    if (i < n) d_cnt[i] = 0;
}

__global__ void k_hist(const int* __restrict__ ei, int E) {
    int e = blockIdx.x * blockDim.x + threadIdx.x;
    if (e < E) atomicAdd(&d_cnt[ei[e]], 1);
}

__global__ void k_scan1(int N) {
    __shared__ int s[32];
    int t = threadIdx.x;
    int i = blockIdx.x * 1024 + t;
    int lane = t & 31, w = t >> 5;
    int c = (i < N) ? d_cnt[i] : 0;
    int v = c;
#pragma unroll
    for (int d = 1; d < 32; d <<= 1) {
        int u = __shfl_up_sync(0xffffffffu, v, d);
        if (lane >= d) v += u;
    }
    if (lane == 31) s[w] = v;
    __syncthreads();
    if (w == 0) {
        int sv = s[lane];
#pragma unroll
        for (int d = 1; d < 32; d <<= 1) {
            int u = __shfl_up_sync(0xffffffffu, sv, d);
            if (lane >= d) sv += u;
        }
        s[lane] = sv;
    }
    __syncthreads();
    int base = (w > 0) ? s[w - 1] : 0;
    int incl = v + base;
    if (i < N) d_off[i] = incl - c;
    if (t == 1023) d_bsum[blockIdx.x] = incl;
}

__global__ void k_scan2(int NB) {
    __shared__ int s[2];
    int t = threadIdx.x;
    int lane = t & 31, w = t >> 5;
    int c = (t < NB) ? d_bsum[t] : 0;
    int v = c;
#pragma unroll
    for (int d = 1; d < 32; d <<= 1) {
        int u = __shfl_up_sync(0xffffffffu, v, d);
        if (lane >= d) v += u;
    }
    if (lane == 31) s[w] = v;
    __syncthreads();
    int base = (w > 0) ? s[0] : 0;
    if (t < NB) d_bbase[t] = v + base - c;
}

__global__ void k_scan3(int N, int E) {
    int i = blockIdx.x * blockDim.x + threadIdx.x;
    if (i < N) {
        int v = d_off[i] + d_bbase[i >> 10];
        d_off[i] = v;
        d_cur[i] = v;
    }
    if (i == 0) d_off[N] = E;
}

__global__ void k_scatter(const int* __restrict__ ei, int E) {
    int e = blockIdx.x * blockDim.x + threadIdx.x;
    if (e < E) {
        int r = ei[e];
        int c = ei[E + e];
        int p = atomicAdd(&d_cur[r], 1);
        d_cols[p] = c;
        d_eid[p]  = e;
    }
}

// ---------------- SpMM: Xh[:,0:128] = sum_{in-edges} h_fp16[col]
template <int FIRST>
__launch_bounds__(256)
__global__ void k_spmm(const float* __restrict__ ea, int N) {
    int gw   = (blockIdx.x * blockDim.x + threadIdx.x) >> 5;
    int lane = threadIdx.x & 31;
    if (gw >= N) return;
    int lo = d_off[gw], hi = d_off[gw + 1];
    float4 acc = make_float4(0.f, 0.f, 0.f, 0.f);
    float2 eacc = make_float2(0.f, 0.f);
    int j = lo;
    for (; j + 4 <= hi; j += 4) {
        int c0 = d_cols[j],     c1 = d_cols[j + 1];
        int c2 = d_cols[j + 2], c3 = d_cols[j + 3];
        H4 v0 = *(const H4*)(d_hh + (size_t)c0 * HDIM + lane * 4);
        H4 v1 = *(const H4*)(d_hh + (size_t)c1 * HDIM + lane * 4);
        H4 v2 = *(const H4*)(d_hh + (size_t)c2 * HDIM + lane * 4);
        H4 v3 = *(const H4*)(d_hh + (size_t)c3 * HDIM + lane * 4);
        if (FIRST) {
            int e0 = d_eid[j],     e1 = d_eid[j + 1];
            int e2 = d_eid[j + 2], e3 = d_eid[j + 3];
            float2 w0 = *(const float2*)(ea + (size_t)e0 * FE + lane * 2);
            float2 w1 = *(const float2*)(ea + (size_t)e1 * FE + lane * 2);
            float2 w2 = *(const float2*)(ea + (size_t)e2 * FE + lane * 2);
            float2 w3 = *(const float2*)(ea + (size_t)e3 * FE + lane * 2);
            eacc.x += (w0.x + w1.x) + (w2.x + w3.x);
            eacc.y += (w0.y + w1.y) + (w2.y + w3.y);
        }
        float2 a0 = __half22float2(v0.a), b0 = __half22float2(v0.b);
        float2 a1 = __half22float2(v1.a), b1 = __half22float2(v1.b);
        float2 a2 = __half22float2(v2.a), b2 = __half22float2(v2.b);
        float2 a3 = __half22float2(v3.a), b3 = __half22float2(v3.b);
        acc.x += (a0.x + a1.x) + (a2.x + a3.x);
        acc.y += (a0.y + a1.y) + (a2.y + a3.y);
        acc.z += (b0.x + b1.x) + (b2.x + b3.x);
        acc.w += (b0.y + b1.y) + (b2.y + b3.y);
    }
    for (; j < hi; j++) {
        int c0 = d_cols[j];
        H4 v0 = *(const H4*)(d_hh + (size_t)c0 * HDIM + lane * 4);
        if (FIRST) {
            int e0 = d_eid[j];
            float2 w0 = *(const float2*)(ea + (size_t)e0 * FE + lane * 2);
            eacc.x += w0.x; eacc.y += w0.y;
        }
        float2 a0 = __half22float2(v0.a), b0 = __half22float2(v0.b);
        acc.x += a0.x; acc.y += a0.y; acc.z += b0.x; acc.w += b0.y;
    }
    H4 st;
    st.a = __floats2half2_rn(acc.x, acc.y);
    st.b = __floats2half2_rn(acc.z, acc.w);
    *(H4*)(d_Xh + (size_t)gw * KX + lane * 4) = st;
    if (FIRST)
        *(__half2*)(d_Xh + (size_t)gw * KX + HDIM + lane * 2) =
            __floats2half2_rn(eacc.x, eacc.y);
}

// ---------------- cp.async helpers ----------------
__device__ __forceinline__ void cpa16(uint32_t dst, const void* src, bool pred) {
    int sz = pred ? 16 : 0;
    asm volatile("cp.async.cg.shared.global [%0], [%1], 16, %2;\n"
                 :: "r"(dst), "l"(src), "r"(sz));
}
__device__ __forceinline__ void cpa_commit() {
    asm volatile("cp.async.commit_group;\n" ::: "memory");
}
template <int Nn>
__device__ __forceinline__ void cpa_wait() {
    asm volatile("cp.async.wait_group %0;\n" :: "n"(Nn) : "memory");
}

// ---------------- unified fp16 m16n8k16 GEMM, double-buffered cp.async ----------------
// C[N,128] = A[N,K](fp16) @ B[128n,K](fp16, n-major) + epilogue
// EPI==0 : d_h = relu(C + bias); d_hh mirror
// EPI==1 : d_h += relu( BN(C/deg + bias) ); d_hh mirror  (A = d_Xh)
template <int K, int EPI>
__launch_bounds__(256)
__global__ void k_gemm_f16(const __half* __restrict__ Aglob,
                           const __half* __restrict__ Bglob,
                           const float* __restrict__ bias,
                           const float* __restrict__ gamma,
                           const float* __restrict__ beta,
                           int N) {
    constexpr int KC = 32;
    constexpr int KTILES = K / KC;
    constexpr int ST = 40;                     // halves per row (80 B), conflict-free frags
    __shared__ __align__(16) __half smA[2][128 * ST];
    __shared__ __align__(16) __half smB[2][128 * ST];

    const __half* A = (EPI == 1) ? (const __half*)d_Xh : Aglob;

    const int tid  = threadIdx.x;
    const int wid  = tid >> 5;
    const int lane = tid & 31;
    const int warp_m = wid & 3;
    const int warp_n = wid >> 2;
    const int gID = lane >> 2;
    const int tig = lane & 3;
    const int rowBase = blockIdx.x * 128;

    // per-thread staging coords: two 16B chunks each for A and B
    const int c0i = tid, c1i = tid + 256;      // chunk ids 0..511
    const int ar0 = c0i >> 2, ak0 = (c0i & 3) * 8;
    const int ar1 = c1i >> 2, ak1 = (c1i & 3) * 8;

    auto prefetch = [&](int kt, int buf) {
        const int k0 = kt * KC;
        uint32_t dA0 = (uint32_t)__cvta_generic_to_shared(&smA[buf][ar0 * ST + ak0]);
        uint32_t dA1 = (uint32_t)__cvta_generic_to_shared(&smA[buf][ar1 * ST + ak1]);
        cpa16(dA0, A + (size_t)(rowBase + ar0) * K + k0 + ak0, rowBase + ar0 < N);
        cpa16(dA1, A + (size_t)(rowBase + ar1) * K + k0 + ak1, rowBase + ar1 < N);
        uint32_t dB0 = (uint32_t)__cvta_generic_to_shared(&smB[buf][ar0 * ST + ak0]);
        uint32_t dB1 = (uint32_t)__cvta_generic_to_shared(&smB[buf][ar1 * ST + ak1]);
        cpa16(dB0, Bglob + (size_t)ar0 * K + k0 + ak0, true);
        cpa16(dB1, Bglob + (size_t)ar1 * K + k0 + ak1, true);
    };

    float acc[2][8][4];
#pragma unroll
    for (int mf = 0; mf < 2; mf++)
#pragma unroll
        for (int nf = 0; nf < 8; nf++)
#pragma unroll
            for (int c = 0; c < 4; c++) acc[mf][nf][c] = 0.f;

    prefetch(0, 0);
    cpa_commit();

    int buf = 0;
    for (int kt = 0; kt < KTILES; kt++) {
        cpa_wait<0>();
        __syncthreads();                       // tile kt ready; prev compute done everywhere
        if (kt + 1 < KTILES) {
            prefetch(kt + 1, buf ^ 1);
            cpa_commit();
        }
        const __half* As = smA[buf];
        const __half* Bs = smB[buf];
#pragma unroll
        for (int ks = 0; ks < 2; ks++) {       // two k16 steps per KC=32
            const int kb = ks * 16;
            uint32_t bfr[8][2];
#pragma unroll
            for (int nf = 0; nf < 8; nf++) {
                int col = warp_n * 64 + nf * 8 + gID;
                bfr[nf][0] = *(const uint32_t*)&Bs[col * ST + kb + 2 * tig];
                bfr[nf][1] = *(const uint32_t*)&Bs[col * ST + kb + 8 + 2 * tig];
            }
#pragma unroll
            for (int mf = 0; mf < 2; mf++) {
                int r0 = warp_m * 32 + mf * 16 + gID;
                uint32_t a0 = *(const uint32_t*)&As[r0 * ST + kb + 2 * tig];
                uint32_t a1 = *(const uint32_t*)&As[(r0 + 8) * ST + kb + 2 * tig];
                uint32_t a2 = *(const uint32_t*)&As[r0 * ST + kb + 8 + 2 * tig];
                uint32_t a3 = *(const uint32_t*)&As[(r0 + 8) * ST + kb + 8 + 2 * tig];
#pragma unroll
                for (int nf = 0; nf < 8; nf++) {
                    asm volatile(
                        "mma.sync.aligned.m16n8k16.row.col.f32.f16.f16.f32 "
                        "{%0,%1,%2,%3}, {%4,%5,%6,%7}, {%8,%9}, {%0,%1,%2,%3};\n"
                        : "+f"(acc[mf][nf][0]), "+f"(acc[mf][nf][1]),
                          "+f"(acc[mf][nf][2]), "+f"(acc[mf][nf][3])
                        : "r"(a0), "r"(a1), "r"(a2), "r"(a3),
                          "r"(bfr[nf][0]), "r"(bfr[nf][1]));
                }
            }
        }
        __syncthreads();                       // done reading buf before it is refilled
        buf ^= 1;
    }

    const float sc = rsqrtf(1.f + BN_EPS);
#pragma unroll
    for (int mf = 0; mf < 2; mf++) {
        int r0 = rowBase + warp_m * 32 + mf * 16 + gID;
        int r1 = r0 + 8;
        float inv0 = 1.f, inv1 = 1.f;
        if (EPI == 1) {
            if (r0 < N) inv0 = 1.f / (float)max(d_cnt[r0], 1);
            if (r1 < N) inv1 = 1.f / (float)max(d_cnt[r1], 1);
        }
#pragma unroll
        for (int nf = 0; nf < 8; nf++) {
            int c0 = warp_n * 64 + nf * 8 + 2 * tig;
#pragma unroll
            for (int cc = 0; cc < 2; cc++) {
                int c = c0 + cc;
                float b = bias[c];
                if (EPI == 0) {
                    if (r0 < N) {
                        float v = fmaxf(acc[mf][nf][cc] + b, 0.f);
                        d_h[(size_t)r0 * HDIM + c] = v;
                        d_hh[(size_t)r0 * HDIM + c] = __float2half_rn(v);
                    }
                    if (r1 < N) {
                        float v = fmaxf(acc[mf][nf][2 + cc] + b, 0.f);
                        d_h[(size_t)r1 * HDIM + c] = v;
                        d_hh[(size_t)r1 * HDIM + c] = __float2half_rn(v);
                    }
                } else {
                    float g = gamma[c] * sc;
                    float be = beta[c];
                    if (r0 < N) {
                        float v = acc[mf][nf][cc] * inv0 + b;
                        v = v * g + be;
                        float nh = d_h[(size_t)r0 * HDIM + c] + fmaxf(v, 0.f);
                        d_h[(size_t)r0 * HDIM + c] = nh;
                        d_hh[(size_t)r0 * HDIM + c] = __float2half_rn(nh);
                    }
                    if (r1 < N) {
                        float v = acc[mf][nf][2 + cc] * inv1 + b;
                        v = v * g + be;
                        float nh = d_h[(size_t)r1 * HDIM + c] + fmaxf(v, 0.f);
                        d_h[(size_t)r1 * HDIM + c] = nh;
                        d_hh[(size_t)r1 * HDIM + c] = __float2half_rn(nh);
                    }
                }
            }
        }
    }
}

// ---------------- fused mean-pool + hidden + head (batch_idx sorted) ----------------
__launch_bounds__(128)
__global__ void k_head(const int* __restrict__ batch,
                       const float* __restrict__ Wh,
                       const float* __restrict__ bh,
                       const float* __restrict__ Wout,
                       const float* __restrict__ bout,
                       float* __restrict__ out, int N) {
    int b = blockIdx.x;
    int t = threadIdx.x;
    __shared__ float gv[HDIM];
    __shared__ float red[HDIM];
    __shared__ int srange[2];
    if (t < 2) {
        int v = b + t;
        int lo = 0, hi = N;
        while (lo < hi) {
            int m = (lo + hi) >> 1;
            if (batch[m] < v) lo = m + 1; else hi = m;
        }
        srange[t] = lo;
    }
    __syncthreads();
    int lo = srange[0], hi = srange[1];
    float s = 0.f;
    for (int r = lo; r < hi; r++) s += d_h[(size_t)r * HDIM + t];
    gv[t] = s / (float)max(hi - lo, 1);
    __syncthreads();
    float hd = bh[t];
#pragma unroll 8
    for (int k = 0; k < HDIM; k++) hd = fmaf(gv[k], Wh[k * HDIM + t], hd);
    hd = fmaxf(hd, 0.f);
    red[t] = hd * Wout[t];
    __syncthreads();
    for (int s2 = 64; s2 > 0; s2 >>= 1) {
        if (t < s2) red[t] += red[t + s2];
        __syncthreads();
    }
    if (t == 0) out[b] = red[0] + bout[0];
}

// ---------------- launch ----------------
extern "C" void kernel_launch(void* const* d_in, const int* in_sizes, int n_in,
                              void* d_out, int out_size) {
    const float* x     = (const float*)d_in[0];
    const int*   ei    = (const int*)  d_in[1];
    const float* ea    = (const float*)d_in[2];
    const int*   batch = (const int*)  d_in[3];
    const float* W_emb = (const float*)d_in[4];
    const float* b_emb = (const float*)d_in[5];
    const float* Wc    = (const float*)d_in[6];
    const float* bc    = (const float*)d_in[7];
    const float* gamma = (const float*)d_in[8];
    const float* beta  = (const float*)d_in[9];
    const float* Wh    = (const float*)d_in[10];
    const float* bh    = (const float*)d_in[11];
    const float* Wout  = (const float*)d_in[12];
    const float* bout  = (const float*)d_in[13];
    float* out = (float*)d_out;

    int N = in_sizes[0] / FN;
    int E = in_sizes[1] / 2;
    int G = out_size;
    int NB = (N + 1023) / 1024;

    int wprep = NLAYER * HDIM * KX + HDIM * KE;
    k_zero_cnt<<<(N + 255) / 256, 256>>>(N);                       // 0
    k_prep_w<<<(wprep + 255) / 256, 256>>>(Wc, W_emb);             // 1
    k_conv_x<<<(N * KE + 255) / 256, 256>>>(x, N);                 // 2
    // embedding GEMM at launch index 3 -> ncu window profiles this
    __half* hemb = nullptr; float* fnul = nullptr;
    {
        // device symbol addresses are resolved inside the kernel; pass d_xh/d_Wembh
        // via small helper: use cudaGetSymbolAddress-free path by dedicated kernel args
    }
    // use symbol-referencing wrappers: pointers obtained through device-side arrays
    // (template EPI==0 path reads Aglob/Bglob params)
    {
        void* pA; void* pB;
        cudaGetSymbolAddress(&pA, d_xh);
        cudaGetSymbolAddress(&pB, d_Wembh);
        k_gemm_f16<KE, 0><<<(N + 127) / 128, 256>>>((const __half*)pA,
                                                    (const __half*)pB,
                                                    b_emb, fnul, fnul, N);  // 3
    }
    k_hist<<<(E + 255) / 256, 256>>>(ei, E);                       // 4
    k_scan1<<<NB, 1024>>>(N);                                      // 5
    k_scan2<<<1, 64>>>(NB);                                        // 6
    k_scan3<<<NB, 1024>>>(N, E);                                   // 7
    k_scatter<<<(E + 255) / 256, 256>>>(ei, E);                    // 8

    void* pWch;
    cudaGetSymbolAddress(&pWch, d_Wch);

    // layer 0: fused h-gather + edge-attr aggregation
    k_spmm<1><<<(N * 32 + 255) / 256, 256>>>(ea, N);
    k_gemm_f16<KX, 1><<<(N + 127) / 128, 256>>>(hemb, (const __half*)pWch,
                                                bc, gamma, beta, N);

    for (int l = 1; l < NLAYER; l++) {
        k_spmm<0><<<(N * 32 + 255) / 256, 256>>>(ea, N);
        k_gemm_f16<KX, 1><<<(N + 127) / 128, 256>>>(
            hemb, (const __half*)pWch + (size_t)l * HDIM * KX,
            bc + l * HDIM, gamma + l * HDIM, beta + l * HDIM, N);
    }

    k_head<<<G, 128>>>(batch, Wh, bh, Wout, bout, out, N);
}